// round 15
// baseline (speedup 1.0000x reference)
#include <cuda_runtime.h>
#include <cuda_fp16.h>
#include <cstdint>

#define BATCH 4
#define TSEQ  4096

typedef unsigned int u32;

// ---------------- device globals (no alloc allowed) ----------------
// fp16, natural [b][t][32] layout. g_q pre-scaled by 32^-0.5 * log2(e).
__device__ __half g_q[BATCH * TSEQ * 32];
__device__ __half g_k[BATCH * TSEQ * 32];
__device__ __half g_v[BATCH * TSEQ * 32];
__device__ float  g_po[BATCH * 32 * 16 * 128 * 32];  // split partial O
__device__ float  g_pl[BATCH * 32 * 16 * 128];       // split partial l
__device__ u32    g_cnt[BATCH * 32];                 // split tickets (reset by finisher)

static __device__ __forceinline__ u32 h2pack(float hi, float lo) {
    u32 d; asm("cvt.rn.f16x2.f32 %0, %1, %2;" : "=r"(d) : "f"(hi), "f"(lo)); return d;
}
static __device__ __forceinline__ u32 h2exp(u32 x) {
    u32 y; asm("ex2.approx.f16x2 %0, %1;" : "=r"(y) : "r"(x)); return y;
}
static __device__ __forceinline__ u32 smem_u32(const void* p) {
    u32 a;
    asm("{ .reg .u64 t; cvta.to.shared.u64 t, %1; cvt.u32.u64 %0, t; }"
        : "=r"(a) : "l"(p));
    return a;
}
static __device__ __forceinline__ void cpasync16(u32 saddr, const void* g) {
    asm volatile("cp.async.ca.shared.global [%0], [%1], 16;" :: "r"(saddr), "l"(g));
}
#define CP_COMMIT()  asm volatile("cp.async.commit_group;" ::: "memory")
#define CP_WAIT(n)   asm volatile("cp.async.wait_group %0;" :: "n"(n) : "memory")

// D += A*B  (m16n8k16, fp16 in, f32 accum)
static __device__ __forceinline__ void mma16(float* d, const u32* a, u32 b0, u32 b1) {
    asm volatile(
        "mma.sync.aligned.m16n8k16.row.col.f32.f16.f16.f32 "
        "{%0,%1,%2,%3}, {%4,%5,%6,%7}, {%8,%9}, {%0,%1,%2,%3};"
        : "+f"(d[0]), "+f"(d[1]), "+f"(d[2]), "+f"(d[3])
        : "r"(a[0]), "r"(a[1]), "r"(a[2]), "r"(a[3]), "r"(b0), "r"(b1));
}
static __device__ __forceinline__ void ldsm4(u32& r0, u32& r1, u32& r2, u32& r3, u32 a) {
    asm volatile("ldmatrix.sync.aligned.m8n8.x4.shared.b16 {%0,%1,%2,%3}, [%4];"
        : "=r"(r0), "=r"(r1), "=r"(r2), "=r"(r3) : "r"(a));
}
static __device__ __forceinline__ void ldsm4t(u32& r0, u32& r1, u32& r2, u32& r3, u32 a) {
    asm volatile("ldmatrix.sync.aligned.m8n8.x4.trans.shared.b16 {%0,%1,%2,%3}, [%4];"
        : "=r"(r0), "=r"(r1), "=r"(r2), "=r"(r3) : "r"(a));
}

// uniform 4-tile (64-key) splits: qtile qi has n=2(qi+1) tiles, s_i=ceil((qi+1)/2)
static __device__ __forceinline__ int nsplits(int i) { return (i + 2) >> 1; }

// ---------------------------------------------------------------------------
// Kernel 1: QKV projection on tensor cores. 256 CTAs x 64 rows, 128 threads.
// ---------------------------------------------------------------------------
__global__ __launch_bounds__(128) void qkv_kernel(
    const float* __restrict__ x,
    const float* __restrict__ Wq,
    const float* __restrict__ Wk,
    const float* __restrict__ Wv)
{
    __shared__ __align__(128) char sW[3][2048];   // [m][h*64B row, swizzled]

    int tid  = threadIdx.x;
    int lane = tid & 31;
    int w    = tid >> 5;
    int g    = lane >> 2;
    int t4   = lane & 3;

    // ---- stage W: thread handles chunk (h = tid>>2, c = tid&3) of each matrix
    {
        int h = tid >> 2, c = tid & 3;
        const float QS = 0.17677669529663687f * 1.4426950408889634f; // 32^-0.5*log2e
        const float* Ws[3] = { Wq, Wk, Wv };
        u32 off = (u32)(h * 64 + ((c ^ ((h >> 1) & 3)) << 4));
#pragma unroll
        for (int m = 0; m < 3; m++) {
            const float4* wp = (const float4*)(Ws[m] + h * 32 + c * 8);
            float4 w0 = wp[0], w1 = wp[1];
            float sc = (m == 0) ? QS : 1.0f;
            uint4 pk;
            pk.x = h2pack(w0.y * sc, w0.x * sc);
            pk.y = h2pack(w0.w * sc, w0.z * sc);
            pk.z = h2pack(w1.y * sc, w1.x * sc);
            pk.w = h2pack(w1.w * sc, w1.z * sc);
            *(uint4*)(sW[m] + off) = pk;
        }
    }

    // ---- A fragments: rows (rA, rA+8), fp32 x -> packed fp16 ----
    int rA = blockIdx.x * 64 + 16 * w + g;
    u32 qa[2][4];
#pragma unroll
    for (int ks = 0; ks < 2; ks++) {
        const float* xA = x + (size_t)rA * 32 + 16 * ks;
        const float* xB = xA + 8 * 32;
        float2 f0 = *(const float2*)(xA + 2 * t4);
        float2 f1 = *(const float2*)(xB + 2 * t4);
        float2 f2 = *(const float2*)(xA + 2 * t4 + 8);
        float2 f3 = *(const float2*)(xB + 2 * t4 + 8);
        qa[ks][0] = h2pack(f0.y, f0.x);
        qa[ks][1] = h2pack(f1.y, f1.x);
        qa[ks][2] = h2pack(f2.y, f2.x);
        qa[ks][3] = h2pack(f3.y, f3.x);
    }
    __syncthreads();

    u32 wlm = (u32)((lane & 7) * 64 + ((((lane >> 3) ^ (((lane & 7) >> 1) & 3))) << 4));
    u32 sWb[3] = { smem_u32(sW[0]), smem_u32(sW[1]), smem_u32(sW[2]) };
    __half* dsts[3] = { g_q, g_k, g_v };

#pragma unroll
    for (int m = 0; m < 3; m++) {
        __half* dst = dsts[m];
#pragma unroll
        for (int j = 0; j < 4; j++) {       // n-tile: outputs h = 8j..8j+7
            u32 b0, b1, b2, b3;
            ldsm4(b0, b1, b2, b3, sWb[m] + (u32)(j * 512) + wlm);
            float c[4] = {0.f, 0.f, 0.f, 0.f};
            mma16(c, qa[0], b0, b1);
            mma16(c, qa[1], b2, b3);
            int col = j * 8 + 2 * t4;
            *(u32*)(dst + (size_t)rA * 32 + col)       = h2pack(c[1], c[0]);
            *(u32*)(dst + (size_t)(rA + 8) * 32 + col) = h2pack(c[3], c[2]);
        }
    }
}

// ---------------------------------------------------------------------------
// Kernel 2: fp16 m16n8k16 flash attention (no-max softmax, uniform split-KV),
// with the split-combine FUSED via an atomic ticket: the last CTA of each
// qtile sums the (L2-resident) partials, normalizes, writes out, and resets
// the ticket counter for graph-replay determinism.
// ---------------------------------------------------------------------------
__global__ __launch_bounds__(256, 3) void attn_kernel(float* __restrict__ out)
{
    __shared__ __align__(128) char sK[2][64 * 64];   // [key][dim] fp16, swizzled
    __shared__ __align__(128) char sV[2][64 * 64];
    __shared__ int sdone;

    int tid  = threadIdx.x;
    int lane = tid & 31;
    int w    = tid >> 5;
    int g    = lane >> 2;     // group id 0..7
    int t4   = lane & 3;      // thread in group
    int b    = blockIdx.y;

    // map blockIdx.x -> (qtile qi, split p)
    int u = blockIdx.x, qi = 0, s = 1;
    for (qi = 0; qi < 32; qi++) {
        s = nsplits(qi);
        if (u < s) break;
        u -= s;
    }
    int p  = u;
    int n  = 2 * (qi + 1);
    int tb = p * 4;
    int te = (tb + 4 < n) ? tb + 4 : n;
    int r0 = qi * 128;
    int rA = r0 + 16 * w + g;     // this lane's first q-row (second = rA+8)

    u32 sKb[2] = { smem_u32(&sK[0][0]), smem_u32(&sK[1][0]) };
    u32 sVb[2] = { smem_u32(&sV[0][0]), smem_u32(&sV[1][0]) };

    // cp.async staging offset (swizzle chunk ^ ((row>>1)&3))
    u32 stoff = (u32)((tid >> 2) * 64 + (((tid & 3) ^ ((tid >> 3) & 3)) << 4));
    // ldmatrix K address offset
    u32 klm = (u32)((lane & 7) * 64 + ((((lane >> 3) ^ (((lane & 7) >> 1) & 3))) << 4));
    // ldmatrix V lane mapping
    int vkey = (lane & 7) + 8 * ((lane >> 3) & 1);
    int vch  = (lane >> 4);

    // ones-column B fragment for l = P·1 (n==0 column all ones)
    u32 bl = (g == 0) ? 0x3C003C00u : 0u;

    // ---- Q fragments ----
    u32 qa[2][4];
    {
        const __half* qA = g_q + ((size_t)b * TSEQ + rA) * 32;
        const __half* qB = qA + 8 * 32;
#pragma unroll
        for (int ks = 0; ks < 2; ks++) {
            qa[ks][0] = *(const u32*)(qA + 16 * ks + 2 * t4);
            qa[ks][1] = *(const u32*)(qB + 16 * ks + 2 * t4);
            qa[ks][2] = *(const u32*)(qA + 16 * ks + 2 * t4 + 8);
            qa[ks][3] = *(const u32*)(qB + 16 * ks + 2 * t4 + 8);
        }
    }

    float oc[4][4];
#pragma unroll
    for (int jd = 0; jd < 4; jd++)
#pragma unroll
        for (int q = 0; q < 4; q++) oc[jd][q] = 0.f;
    float lc[4] = {0.f, 0.f, 0.f, 0.f};   // l accumulator (col 0 meaningful)

    // ---- stage tile tb into buffer 0 ----
    {
        const char* kg = (const char*)(g_k + ((size_t)b * TSEQ + tb * 64) * 32);
        const char* vg = (const char*)(g_v + ((size_t)b * TSEQ + tb * 64) * 32);
        u32 goff = (u32)((tid >> 2) * 64 + (tid & 3) * 16);
        cpasync16(sKb[0] + stoff, kg + goff);
        cpasync16(sVb[0] + stoff, vg + goff);
        CP_COMMIT();
    }

    int cur = 0;

    for (int t = tb; t < te; t++) {
        bool havenext = (t + 1 < te);
        if (havenext) {
            const char* kg = (const char*)(g_k + ((size_t)b * TSEQ + (t + 1) * 64) * 32);
            const char* vg = (const char*)(g_v + ((size_t)b * TSEQ + (t + 1) * 64) * 32);
            u32 goff = (u32)((tid >> 2) * 64 + (tid & 3) * 16);
            cpasync16(sKb[cur ^ 1] + stoff, kg + goff);
            cpasync16(sVb[cur ^ 1] + stoff, vg + goff);
            CP_COMMIT();
            CP_WAIT(1);
        } else {
            CP_WAIT(0);
        }
        __syncthreads();

        u32 cK = sKb[cur];
        u32 cV = sVb[cur];
        bool domask = (t >= 2 * qi);

        u32 pp01 = 0, pp23 = 0;   // packed scores of even chunk, pending PV

#pragma unroll
        for (int j = 0; j < 8; j++) {
            // ---- K frags: one ldmatrix.x4 per 8-key chunk ----
            u32 kb0, kb1, kb2, kb3;
            ldsm4(kb0, kb1, kb2, kb3, cK + (u32)(j * 512) + klm);

            float sa[4] = {0.f, 0.f, 0.f, 0.f};
            mma16(sa, qa[0], kb0, kb1);
            mma16(sa, qa[1], kb2, kb3);

            // ---- mask (pre-exp) + pack to fp16 pairs ----
            int ct = t * 64 + 8 * j + 2 * t4;
            if (domask) {
                if (ct     > rA)     sa[0] = -1e30f;   // -> fp16 -inf -> exp 0
                if (ct + 1 > rA)     sa[1] = -1e30f;
                if (ct     > rA + 8) sa[2] = -1e30f;
                if (ct + 1 > rA + 8) sa[3] = -1e30f;
            }
            u32 p01 = h2pack(sa[1], sa[0]);
            u32 p23 = h2pack(sa[3], sa[2]);

            if ((j & 1) == 0) {
                pp01 = p01; pp23 = p23;
            } else {
                // ---- packed exp: P frags for the 16-key group c = j>>1 ----
                u32 pa[4];
                pa[0] = h2exp(pp01);
                pa[1] = h2exp(pp23);
                pa[2] = h2exp(p01);
                pa[3] = h2exp(p23);
                int c = j >> 1;
#pragma unroll
                for (int pr = 0; pr < 2; pr++) {
                    u32 vb0, vb1, vb2, vb3;
                    int key = c * 16 + vkey;
                    int ch  = 2 * pr + vch;
                    u32 va = cV + (u32)(key * 64 + ((ch ^ ((key >> 1) & 3)) << 4));
                    ldsm4t(vb0, vb1, vb2, vb3, va);
                    mma16(oc[2 * pr],     pa, vb0, vb1);
                    mma16(oc[2 * pr + 1], pa, vb2, vb3);
                }
                mma16(lc, pa, bl, bl);       // l += P · ones-column
            }
        }

        __syncthreads();
        cur ^= 1;
    }

    // ---- extract row sums: l lives in col 0 (t4==0 lanes), c0/c2 ----
    float ls0 = __shfl_sync(0xffffffffu, lc[0], lane & ~3);
    float ls1 = __shfl_sync(0xffffffffu, lc[2], lane & ~3);

    // ---- epilogue ----
    if (s == 1) {
        float i0 = 1.0f / ls0;
        float i1 = 1.0f / ls1;
        float* oA = out + ((size_t)b * TSEQ + rA) * 32;
        float* oB = oA + 8 * 32;
#pragma unroll
        for (int jd = 0; jd < 4; jd++) {
            *(float2*)&oA[8 * jd + 2 * t4] = make_float2(oc[jd][0] * i0, oc[jd][1] * i0);
            *(float2*)&oB[8 * jd + 2 * t4] = make_float2(oc[jd][2] * i1, oc[jd][3] * i1);
        }
        return;
    }

    // ---- multi-split: write partials, then ticket; last CTA combines ----
    size_t qbase = (size_t)(b * 32 + qi) * 16;
    {
        size_t base = (qbase + p) * 128;
        int lr = 16 * w + g;
        float* pA = g_po + (base + lr) * 32;
        float* pB = pA + 8 * 32;
#pragma unroll
        for (int jd = 0; jd < 4; jd++) {
            *(float2*)&pA[8 * jd + 2 * t4] = make_float2(oc[jd][0], oc[jd][1]);
            *(float2*)&pB[8 * jd + 2 * t4] = make_float2(oc[jd][2], oc[jd][3]);
        }
        if (t4 == 0) {
            g_pl[base + lr]     = ls0;
            g_pl[base + lr + 8] = ls1;
        }
    }
    __threadfence();                       // publish partials before ticket
    __syncthreads();
    if (tid == 0)
        sdone = (atomicAdd(&g_cnt[b * 32 + qi], 1u) == (u32)(s - 1));
    __syncthreads();
    if (!sdone) return;
    __threadfence();                       // acquire side: see all partials

    // ---- finisher: combine s partials for this qtile (L2-resident) ----
    {
        int r = tid >> 1;                  // row 0..127
        int hgrp = tid & 1;                // half of the 32 dims (16 each)
        float l = 0.f;
        for (int pp = 0; pp < s; pp++)
            l += g_pl[(qbase + pp) * 128 + r];
        float inv = 1.0f / l;

        float4 o[4];
#pragma unroll
        for (int j = 0; j < 4; j++) o[j] = make_float4(0.f, 0.f, 0.f, 0.f);
        for (int pp = 0; pp < s; pp++) {
            const float4* src = (const float4*)(g_po +
                ((qbase + pp) * 128 + r) * 32 + hgrp * 16);
#pragma unroll
            for (int j = 0; j < 4; j++) {
                float4 a = src[j];
                o[j].x += a.x; o[j].y += a.y; o[j].z += a.z; o[j].w += a.w;
            }
        }
        float4* op = (float4*)(out + ((size_t)b * TSEQ + r0 + r) * 32 + hgrp * 16);
#pragma unroll
        for (int j = 0; j < 4; j++) {
            o[j].x *= inv; o[j].y *= inv; o[j].z *= inv; o[j].w *= inv;
            op[j] = o[j];
        }
    }
    if (tid == 0) g_cnt[b * 32 + qi] = 0;  // reset for next graph replay
}

// ---------------------------------------------------------------------------
extern "C" void kernel_launch(void* const* d_in, const int* in_sizes, int n_in,
                              void* d_out, int out_size)
{
    const float* x  = (const float*)d_in[0];
    const float* Wq = (const float*)d_in[1];
    const float* Wk = (const float*)d_in[2];
    const float* Wv = (const float*)d_in[3];
    float* out = (float*)d_out;

    qkv_kernel<<<(BATCH * TSEQ) / 64, 128>>>(x, Wq, Wk, Wv);

    dim3 grid(272, BATCH);              // sum_i ceil((i+1)/2) = 272 per batch
    attn_kernel<<<grid, 256>>>(out);
}

// round 16
// speedup vs baseline: 1.0894x; 1.0894x over previous
#include <cuda_runtime.h>
#include <cuda_fp16.h>
#include <cstdint>

#define BATCH 4
#define TSEQ  4096

typedef unsigned int u32;

// ---------------- device globals (no alloc allowed) ----------------
// fp16, natural [b][t][32] layout. g_q pre-scaled by 32^-0.5 * log2(e).
__device__ __half g_q[BATCH * TSEQ * 32];
__device__ __half g_k[BATCH * TSEQ * 32];
__device__ __half g_v[BATCH * TSEQ * 32];
__device__ float  g_po[BATCH * 32 * 16 * 128 * 32];  // split partial O
__device__ float  g_pl[BATCH * 32 * 16 * 128];       // split partial l

static __device__ __forceinline__ u32 h2pack(float hi, float lo) {
    u32 d; asm("cvt.rn.f16x2.f32 %0, %1, %2;" : "=r"(d) : "f"(hi), "f"(lo)); return d;
}
static __device__ __forceinline__ u32 h2exp(u32 x) {
    u32 y; asm("ex2.approx.f16x2 %0, %1;" : "=r"(y) : "r"(x)); return y;
}
static __device__ __forceinline__ u32 smem_u32(const void* p) {
    u32 a;
    asm("{ .reg .u64 t; cvta.to.shared.u64 t, %1; cvt.u32.u64 %0, t; }"
        : "=r"(a) : "l"(p));
    return a;
}
static __device__ __forceinline__ void cpasync16(u32 saddr, const void* g) {
    asm volatile("cp.async.ca.shared.global [%0], [%1], 16;" :: "r"(saddr), "l"(g));
}
#define CP_COMMIT()  asm volatile("cp.async.commit_group;" ::: "memory")
#define CP_WAIT(n)   asm volatile("cp.async.wait_group %0;" :: "n"(n) : "memory")

// D += A*B  (m16n8k16, fp16 in, f32 accum)
static __device__ __forceinline__ void mma16(float* d, const u32* a, u32 b0, u32 b1) {
    asm volatile(
        "mma.sync.aligned.m16n8k16.row.col.f32.f16.f16.f32 "
        "{%0,%1,%2,%3}, {%4,%5,%6,%7}, {%8,%9}, {%0,%1,%2,%3};"
        : "+f"(d[0]), "+f"(d[1]), "+f"(d[2]), "+f"(d[3])
        : "r"(a[0]), "r"(a[1]), "r"(a[2]), "r"(a[3]), "r"(b0), "r"(b1));
}
static __device__ __forceinline__ void ldsm4(u32& r0, u32& r1, u32& r2, u32& r3, u32 a) {
    asm volatile("ldmatrix.sync.aligned.m8n8.x4.shared.b16 {%0,%1,%2,%3}, [%4];"
        : "=r"(r0), "=r"(r1), "=r"(r2), "=r"(r3) : "r"(a));
}
static __device__ __forceinline__ void ldsm4t(u32& r0, u32& r1, u32& r2, u32& r3, u32 a) {
    asm volatile("ldmatrix.sync.aligned.m8n8.x4.trans.shared.b16 {%0,%1,%2,%3}, [%4];"
        : "=r"(r0), "=r"(r1), "=r"(r2), "=r"(r3) : "r"(a));
}

// uniform 4-tile (64-key) splits: qtile qi has n=2(qi+1) tiles, s_i=ceil((qi+1)/2)
static __device__ __forceinline__ int nsplits(int i) { return (i + 2) >> 1; }

// ---------------------------------------------------------------------------
// Kernel 1: QKV projection on tensor cores. 256 CTAs x 64 rows, 128 threads.
// (proven R11 version)
// ---------------------------------------------------------------------------
__global__ __launch_bounds__(128) void qkv_kernel(
    const float* __restrict__ x,
    const float* __restrict__ Wq,
    const float* __restrict__ Wk,
    const float* __restrict__ Wv)
{
    __shared__ __align__(128) char sW[3][2048];   // [m][h*64B row, swizzled]

    int tid  = threadIdx.x;
    int lane = tid & 31;
    int w    = tid >> 5;
    int g    = lane >> 2;
    int t4   = lane & 3;

    {
        int h = tid >> 2, c = tid & 3;
        const float QS = 0.17677669529663687f * 1.4426950408889634f; // 32^-0.5*log2e
        const float* Ws[3] = { Wq, Wk, Wv };
        u32 off = (u32)(h * 64 + ((c ^ ((h >> 1) & 3)) << 4));
#pragma unroll
        for (int m = 0; m < 3; m++) {
            const float4* wp = (const float4*)(Ws[m] + h * 32 + c * 8);
            float4 w0 = wp[0], w1 = wp[1];
            float sc = (m == 0) ? QS : 1.0f;
            uint4 pk;
            pk.x = h2pack(w0.y * sc, w0.x * sc);
            pk.y = h2pack(w0.w * sc, w0.z * sc);
            pk.z = h2pack(w1.y * sc, w1.x * sc);
            pk.w = h2pack(w1.w * sc, w1.z * sc);
            *(uint4*)(sW[m] + off) = pk;
        }
    }

    int rA = blockIdx.x * 64 + 16 * w + g;
    u32 qa[2][4];
#pragma unroll
    for (int ks = 0; ks < 2; ks++) {
        const float* xA = x + (size_t)rA * 32 + 16 * ks;
        const float* xB = xA + 8 * 32;
        float2 f0 = *(const float2*)(xA + 2 * t4);
        float2 f1 = *(const float2*)(xB + 2 * t4);
        float2 f2 = *(const float2*)(xA + 2 * t4 + 8);
        float2 f3 = *(const float2*)(xB + 2 * t4 + 8);
        qa[ks][0] = h2pack(f0.y, f0.x);
        qa[ks][1] = h2pack(f1.y, f1.x);
        qa[ks][2] = h2pack(f2.y, f2.x);
        qa[ks][3] = h2pack(f3.y, f3.x);
    }
    __syncthreads();

    u32 wlm = (u32)((lane & 7) * 64 + ((((lane >> 3) ^ (((lane & 7) >> 1) & 3))) << 4));
    u32 sWb[3] = { smem_u32(sW[0]), smem_u32(sW[1]), smem_u32(sW[2]) };
    __half* dsts[3] = { g_q, g_k, g_v };

#pragma unroll
    for (int m = 0; m < 3; m++) {
        __half* dst = dsts[m];
#pragma unroll
        for (int j = 0; j < 4; j++) {
            u32 b0, b1, b2, b3;
            ldsm4(b0, b1, b2, b3, sWb[m] + (u32)(j * 512) + wlm);
            float c[4] = {0.f, 0.f, 0.f, 0.f};
            mma16(c, qa[0], b0, b1);
            mma16(c, qa[1], b2, b3);
            int col = j * 8 + 2 * t4;
            *(u32*)(dst + (size_t)rA * 32 + col)       = h2pack(c[1], c[0]);
            *(u32*)(dst + (size_t)(rA + 8) * 32 + col) = h2pack(c[3], c[2]);
        }
    }
}

// ---------------------------------------------------------------------------
// Kernel 2: fp16 m16n8k16 flash attention (no-max softmax, uniform split-KV).
// CTA = 128 threads = 4 warps x 32 q-rows (TWO m16 tiles per warp): K/V
// fragments shared across both m-tiles -> half the ldmatrix per unit work,
// two independent S-mma chains per chunk.
// ---------------------------------------------------------------------------
__global__ __launch_bounds__(128, 4) void attn_kernel(float* __restrict__ out)
{
    __shared__ __align__(128) char sK[2][64 * 64];   // [key][dim] fp16, swizzled
    __shared__ __align__(128) char sV[2][64 * 64];

    int tid  = threadIdx.x;
    int lane = tid & 31;
    int w    = tid >> 5;      // 0..3
    int g    = lane >> 2;     // group id 0..7
    int t4   = lane & 3;      // thread in group
    int b    = blockIdx.y;

    // map blockIdx.x -> (qtile qi, split p)
    int u = blockIdx.x, qi = 0, s = 1;
    for (qi = 0; qi < 32; qi++) {
        s = nsplits(qi);
        if (u < s) break;
        u -= s;
    }
    int p  = u;
    int n  = 2 * (qi + 1);
    int tb = p * 4;
    int te = (tb + 4 < n) ? tb + 4 : n;
    int r0 = qi * 128;
    int rA = r0 + 32 * w + g;     // mt0 first row; mt1 first row = rA+16

    u32 sKb[2] = { smem_u32(&sK[0][0]), smem_u32(&sK[1][0]) };
    u32 sVb[2] = { smem_u32(&sV[0][0]), smem_u32(&sV[1][0]) };

    // ldmatrix K address offset (per-lane, warp-invariant)
    u32 klm = (u32)((lane & 7) * 64 + ((((lane >> 3) ^ (((lane & 7) >> 1) & 3))) << 4));
    // ldmatrix V lane mapping
    int vkey = (lane & 7) + 8 * ((lane >> 3) & 1);
    int vch  = (lane >> 4);

    // ones-column B fragment for l = P·1
    u32 bl = (g == 0) ? 0x3C003C00u : 0u;

    // ---- Q fragments for both m-tiles ----
    u32 qa[2][2][4];
#pragma unroll
    for (int mt = 0; mt < 2; mt++) {
        const __half* qA = g_q + ((size_t)b * TSEQ + rA + 16 * mt) * 32;
        const __half* qB = qA + 8 * 32;
#pragma unroll
        for (int ks = 0; ks < 2; ks++) {
            qa[mt][ks][0] = *(const u32*)(qA + 16 * ks + 2 * t4);
            qa[mt][ks][1] = *(const u32*)(qB + 16 * ks + 2 * t4);
            qa[mt][ks][2] = *(const u32*)(qA + 16 * ks + 2 * t4 + 8);
            qa[mt][ks][3] = *(const u32*)(qB + 16 * ks + 2 * t4 + 8);
        }
    }

    float oc[2][4][4];
#pragma unroll
    for (int mt = 0; mt < 2; mt++)
#pragma unroll
        for (int jd = 0; jd < 4; jd++)
#pragma unroll
            for (int q = 0; q < 4; q++) oc[mt][jd][q] = 0.f;
    float lc[2][4];
#pragma unroll
    for (int mt = 0; mt < 2; mt++)
#pragma unroll
        for (int q = 0; q < 4; q++) lc[mt][q] = 0.f;

    // ---- stage tile tb into buffer 0 (128 threads x 2 iters each) ----
    {
        const char* kg = (const char*)(g_k + ((size_t)b * TSEQ + tb * 64) * 32);
        const char* vg = (const char*)(g_v + ((size_t)b * TSEQ + tb * 64) * 32);
#pragma unroll
        for (int i = 0; i < 2; i++) {
            int fi = tid + 128 * i;
            u32 st = (u32)((fi >> 2) * 64 + (((fi & 3) ^ ((fi >> 3) & 3)) << 4));
            u32 go = (u32)((fi >> 2) * 64 + (fi & 3) * 16);
            cpasync16(sKb[0] + st, kg + go);
            cpasync16(sVb[0] + st, vg + go);
        }
        CP_COMMIT();
    }

    int cur = 0;

    for (int t = tb; t < te; t++) {
        bool havenext = (t + 1 < te);
        if (havenext) {
            const char* kg = (const char*)(g_k + ((size_t)b * TSEQ + (t + 1) * 64) * 32);
            const char* vg = (const char*)(g_v + ((size_t)b * TSEQ + (t + 1) * 64) * 32);
#pragma unroll
            for (int i = 0; i < 2; i++) {
                int fi = tid + 128 * i;
                u32 st = (u32)((fi >> 2) * 64 + (((fi & 3) ^ ((fi >> 3) & 3)) << 4));
                u32 go = (u32)((fi >> 2) * 64 + (fi & 3) * 16);
                cpasync16(sKb[cur ^ 1] + st, kg + go);
                cpasync16(sVb[cur ^ 1] + st, vg + go);
            }
            CP_COMMIT();
            CP_WAIT(1);
        } else {
            CP_WAIT(0);
        }
        __syncthreads();

        u32 cK = sKb[cur];
        u32 cV = sVb[cur];
        bool domask = (t >= 2 * qi);

        u32 pp[2][2];             // packed scores of even chunk, per m-tile

#pragma unroll
        for (int j = 0; j < 8; j++) {
            // ---- K frags: ONE ldmatrix.x4 serves BOTH m-tiles ----
            u32 kb0, kb1, kb2, kb3;
            ldsm4(kb0, kb1, kb2, kb3, cK + (u32)(j * 512) + klm);

            // ---- two independent S chains ----
            float s0[4] = {0.f, 0.f, 0.f, 0.f};
            float s1[4] = {0.f, 0.f, 0.f, 0.f};
            mma16(s0, qa[0][0], kb0, kb1);
            mma16(s1, qa[1][0], kb0, kb1);
            mma16(s0, qa[0][1], kb2, kb3);
            mma16(s1, qa[1][1], kb2, kb3);

            // ---- mask (pre-exp) + pack ----
            int ct = t * 64 + 8 * j + 2 * t4;
            if (domask) {
                if (ct     > rA)      s0[0] = -1e30f;
                if (ct + 1 > rA)      s0[1] = -1e30f;
                if (ct     > rA + 8)  s0[2] = -1e30f;
                if (ct + 1 > rA + 8)  s0[3] = -1e30f;
                if (ct     > rA + 16) s1[0] = -1e30f;
                if (ct + 1 > rA + 16) s1[1] = -1e30f;
                if (ct     > rA + 24) s1[2] = -1e30f;
                if (ct + 1 > rA + 24) s1[3] = -1e30f;
            }
            u32 q01_0 = h2pack(s0[1], s0[0]);
            u32 q23_0 = h2pack(s0[3], s0[2]);
            u32 q01_1 = h2pack(s1[1], s1[0]);
            u32 q23_1 = h2pack(s1[3], s1[2]);

            if ((j & 1) == 0) {
                pp[0][0] = q01_0; pp[0][1] = q23_0;
                pp[1][0] = q01_1; pp[1][1] = q23_1;
            } else {
                // ---- packed exp: P frags per m-tile ----
                u32 pa0[4], pa1[4];
                pa0[0] = h2exp(pp[0][0]);
                pa0[1] = h2exp(pp[0][1]);
                pa0[2] = h2exp(q01_0);
                pa0[3] = h2exp(q23_0);
                pa1[0] = h2exp(pp[1][0]);
                pa1[1] = h2exp(pp[1][1]);
                pa1[2] = h2exp(q01_1);
                pa1[3] = h2exp(q23_1);
                int c = j >> 1;
#pragma unroll
                for (int pr = 0; pr < 2; pr++) {
                    u32 vb0, vb1, vb2, vb3;
                    int key = c * 16 + vkey;
                    int ch  = 2 * pr + vch;
                    u32 va = cV + (u32)(key * 64 + ((ch ^ ((key >> 1) & 3)) << 4));
                    ldsm4t(vb0, vb1, vb2, vb3, va);
                    mma16(oc[0][2 * pr],     pa0, vb0, vb1);
                    mma16(oc[1][2 * pr],     pa1, vb0, vb1);
                    mma16(oc[0][2 * pr + 1], pa0, vb2, vb3);
                    mma16(oc[1][2 * pr + 1], pa1, vb2, vb3);
                }
                mma16(lc[0], pa0, bl, bl);
                mma16(lc[1], pa1, bl, bl);
            }
        }

        __syncthreads();
        cur ^= 1;
    }

    // ---- row sums per m-tile (col 0 lanes broadcast) ----
    float ls0[2], ls1[2];
#pragma unroll
    for (int mt = 0; mt < 2; mt++) {
        ls0[mt] = __shfl_sync(0xffffffffu, lc[mt][0], lane & ~3);
        ls1[mt] = __shfl_sync(0xffffffffu, lc[mt][2], lane & ~3);
    }

    // ---- epilogue ----
    if (s == 1) {
#pragma unroll
        for (int mt = 0; mt < 2; mt++) {
            float i0 = 1.0f / ls0[mt];
            float i1 = 1.0f / ls1[mt];
            float* oA = out + ((size_t)b * TSEQ + rA + 16 * mt) * 32;
            float* oB = oA + 8 * 32;
#pragma unroll
            for (int jd = 0; jd < 4; jd++) {
                *(float2*)&oA[8 * jd + 2 * t4] =
                    make_float2(oc[mt][jd][0] * i0, oc[mt][jd][1] * i0);
                *(float2*)&oB[8 * jd + 2 * t4] =
                    make_float2(oc[mt][jd][2] * i1, oc[mt][jd][3] * i1);
            }
        }
    } else {
        size_t base = ((size_t)(b * 32 + qi) * 16 + p) * 128;
#pragma unroll
        for (int mt = 0; mt < 2; mt++) {
            int lr = 32 * w + 16 * mt + g;
            float* pA = g_po + (base + lr) * 32;
            float* pB = pA + 8 * 32;
#pragma unroll
            for (int jd = 0; jd < 4; jd++) {
                *(float2*)&pA[8 * jd + 2 * t4] = make_float2(oc[mt][jd][0], oc[mt][jd][1]);
                *(float2*)&pB[8 * jd + 2 * t4] = make_float2(oc[mt][jd][2], oc[mt][jd][3]);
            }
            if (t4 == 0) {
                g_pl[base + lr]     = ls0[mt];
                g_pl[base + lr + 8] = ls1[mt];
            }
        }
    }
}

// ---------------------------------------------------------------------------
// Kernel 3: combine split partials: out = sum_p O_p / sum_p l_p
// ---------------------------------------------------------------------------
__global__ __launch_bounds__(128) void combine_kernel(float* __restrict__ out)
{
    int qi = blockIdx.x, b = blockIdx.y, r = threadIdx.x;
    int s = nsplits(qi);
    if (s < 2) return;

    float l = 0.f;
    for (int p = 0; p < s; p++)
        l += g_pl[((size_t)(b * 32 + qi) * 16 + p) * 128 + r];
    float inv = 1.0f / l;

    float4 o[8];
#pragma unroll
    for (int j = 0; j < 8; j++) o[j] = make_float4(0.f, 0.f, 0.f, 0.f);
    for (int p = 0; p < s; p++) {
        const float4* pp = (const float4*)(g_po +
            (((size_t)(b * 32 + qi) * 16 + p) * 128 + r) * 32);
#pragma unroll
        for (int j = 0; j < 8; j++) {
            float4 a = pp[j];
            o[j].x += a.x; o[j].y += a.y; o[j].z += a.z; o[j].w += a.w;
        }
    }
    float4* op = (float4*)(out + ((size_t)b * TSEQ + qi * 128 + r) * 32);
#pragma unroll
    for (int j = 0; j < 8; j++) {
        o[j].x *= inv; o[j].y *= inv; o[j].z *= inv; o[j].w *= inv;
        op[j] = o[j];
    }
}

// ---------------------------------------------------------------------------
extern "C" void kernel_launch(void* const* d_in, const int* in_sizes, int n_in,
                              void* d_out, int out_size)
{
    const float* x  = (const float*)d_in[0];
    const float* Wq = (const float*)d_in[1];
    const float* Wk = (const float*)d_in[2];
    const float* Wv = (const float*)d_in[3];
    float* out = (float*)d_out;

    qkv_kernel<<<(BATCH * TSEQ) / 64, 128>>>(x, Wq, Wk, Wv);

    dim3 grid(272, BATCH);              // sum_i ceil((i+1)/2) = 272 per batch
    attn_kernel<<<grid, 128>>>(out);

    combine_kernel<<<dim3(32, BATCH), 128>>>(out);
}

// round 17
// speedup vs baseline: 1.0963x; 1.0063x over previous
#include <cuda_runtime.h>
#include <cuda_fp16.h>
#include <cstdint>

#define BATCH 4
#define TSEQ  4096

typedef unsigned int u32;

// ---------------- device globals (no alloc allowed) ----------------
// fp16, natural [b][t][32] layout. g_q pre-scaled by 32^-0.5 * log2(e).
__device__ __half g_q[BATCH * TSEQ * 32];
__device__ __half g_k[BATCH * TSEQ * 32];
__device__ __half g_v[BATCH * TSEQ * 32];
__device__ float  g_po[BATCH * 32 * 16 * 128 * 32];  // split partial O
__device__ float  g_pl[BATCH * 32 * 16 * 128];       // split partial l

static __device__ __forceinline__ u32 h2pack(float hi, float lo) {
    u32 d; asm("cvt.rn.f16x2.f32 %0, %1, %2;" : "=r"(d) : "f"(hi), "f"(lo)); return d;
}
static __device__ __forceinline__ u32 h2exp(u32 x) {
    u32 y; asm("ex2.approx.f16x2 %0, %1;" : "=r"(y) : "r"(x)); return y;
}
static __device__ __forceinline__ u32 smem_u32(const void* p) {
    u32 a;
    asm("{ .reg .u64 t; cvta.to.shared.u64 t, %1; cvt.u32.u64 %0, t; }"
        : "=r"(a) : "l"(p));
    return a;
}
static __device__ __forceinline__ void cpasync16(u32 saddr, const void* g) {
    asm volatile("cp.async.ca.shared.global [%0], [%1], 16;" :: "r"(saddr), "l"(g));
}
#define CP_COMMIT()  asm volatile("cp.async.commit_group;" ::: "memory")
#define CP_WAIT(n)   asm volatile("cp.async.wait_group %0;" :: "n"(n) : "memory")

// D += A*B  (m16n8k16, fp16 in, f32 accum)
static __device__ __forceinline__ void mma16(float* d, const u32* a, u32 b0, u32 b1) {
    asm volatile(
        "mma.sync.aligned.m16n8k16.row.col.f32.f16.f16.f32 "
        "{%0,%1,%2,%3}, {%4,%5,%6,%7}, {%8,%9}, {%0,%1,%2,%3};"
        : "+f"(d[0]), "+f"(d[1]), "+f"(d[2]), "+f"(d[3])
        : "r"(a[0]), "r"(a[1]), "r"(a[2]), "r"(a[3]), "r"(b0), "r"(b1));
}
static __device__ __forceinline__ void ldsm4(u32& r0, u32& r1, u32& r2, u32& r3, u32 a) {
    asm volatile("ldmatrix.sync.aligned.m8n8.x4.shared.b16 {%0,%1,%2,%3}, [%4];"
        : "=r"(r0), "=r"(r1), "=r"(r2), "=r"(r3) : "r"(a));
}
static __device__ __forceinline__ void ldsm4t(u32& r0, u32& r1, u32& r2, u32& r3, u32 a) {
    asm volatile("ldmatrix.sync.aligned.m8n8.x4.trans.shared.b16 {%0,%1,%2,%3}, [%4];"
        : "=r"(r0), "=r"(r1), "=r"(r2), "=r"(r3) : "r"(a));
}

// uniform 4-tile (64-key) splits: qtile qi has n=2(qi+1) tiles, s_i=ceil((qi+1)/2)
static __device__ __forceinline__ int nsplits(int i) { return (i + 2) >> 1; }

// ---------------------------------------------------------------------------
// Kernel 1: QKV projection on tensor cores. 256 CTAs x 64 rows, 128 threads.
// (proven R11/R16 version)
// ---------------------------------------------------------------------------
__global__ __launch_bounds__(128) void qkv_kernel(
    const float* __restrict__ x,
    const float* __restrict__ Wq,
    const float* __restrict__ Wk,
    const float* __restrict__ Wv)
{
    __shared__ __align__(128) char sW[3][2048];   // [m][h*64B row, swizzled]

    int tid  = threadIdx.x;
    int lane = tid & 31;
    int w    = tid >> 5;
    int g    = lane >> 2;
    int t4   = lane & 3;

    {
        int h = tid >> 2, c = tid & 3;
        const float QS = 0.17677669529663687f * 1.4426950408889634f; // 32^-0.5*log2e
        const float* Ws[3] = { Wq, Wk, Wv };
        u32 off = (u32)(h * 64 + ((c ^ ((h >> 1) & 3)) << 4));
#pragma unroll
        for (int m = 0; m < 3; m++) {
            const float4* wp = (const float4*)(Ws[m] + h * 32 + c * 8);
            float4 w0 = wp[0], w1 = wp[1];
            float sc = (m == 0) ? QS : 1.0f;
            uint4 pk;
            pk.x = h2pack(w0.y * sc, w0.x * sc);
            pk.y = h2pack(w0.w * sc, w0.z * sc);
            pk.z = h2pack(w1.y * sc, w1.x * sc);
            pk.w = h2pack(w1.w * sc, w1.z * sc);
            *(uint4*)(sW[m] + off) = pk;
        }
    }

    int rA = blockIdx.x * 64 + 16 * w + g;
    u32 qa[2][4];
#pragma unroll
    for (int ks = 0; ks < 2; ks++) {
        const float* xA = x + (size_t)rA * 32 + 16 * ks;
        const float* xB = xA + 8 * 32;
        float2 f0 = *(const float2*)(xA + 2 * t4);
        float2 f1 = *(const float2*)(xB + 2 * t4);
        float2 f2 = *(const float2*)(xA + 2 * t4 + 8);
        float2 f3 = *(const float2*)(xB + 2 * t4 + 8);
        qa[ks][0] = h2pack(f0.y, f0.x);
        qa[ks][1] = h2pack(f1.y, f1.x);
        qa[ks][2] = h2pack(f2.y, f2.x);
        qa[ks][3] = h2pack(f3.y, f3.x);
    }
    __syncthreads();

    u32 wlm = (u32)((lane & 7) * 64 + ((((lane >> 3) ^ (((lane & 7) >> 1) & 3))) << 4));
    u32 sWb[3] = { smem_u32(sW[0]), smem_u32(sW[1]), smem_u32(sW[2]) };
    __half* dsts[3] = { g_q, g_k, g_v };

#pragma unroll
    for (int m = 0; m < 3; m++) {
        __half* dst = dsts[m];
#pragma unroll
        for (int j = 0; j < 4; j++) {
            u32 b0, b1, b2, b3;
            ldsm4(b0, b1, b2, b3, sWb[m] + (u32)(j * 512) + wlm);
            float c[4] = {0.f, 0.f, 0.f, 0.f};
            mma16(c, qa[0], b0, b1);
            mma16(c, qa[1], b2, b3);
            int col = j * 8 + 2 * t4;
            *(u32*)(dst + (size_t)rA * 32 + col)       = h2pack(c[1], c[0]);
            *(u32*)(dst + (size_t)(rA + 8) * 32 + col) = h2pack(c[3], c[2]);
        }
    }
}

// ---------------------------------------------------------------------------
// Kernel 2: fp16 m16n8k16 flash attention (no-max softmax, uniform split-KV).
// CTA = 128 threads = 4 warps x 32 q-rows (two m16 tiles per warp).
// NEW: software-pipelined fragment loads — next 16-key group's K/V ldmatrix
// issue under the current group's PV mma stretch (register double-buffered).
// ---------------------------------------------------------------------------
__global__ __launch_bounds__(128, 4) void attn_kernel(float* __restrict__ out)
{
    __shared__ __align__(128) char sK[2][64 * 64];   // [key][dim] fp16, swizzled
    __shared__ __align__(128) char sV[2][64 * 64];

    int tid  = threadIdx.x;
    int lane = tid & 31;
    int w    = tid >> 5;      // 0..3
    int g    = lane >> 2;     // group id 0..7
    int t4   = lane & 3;      // thread in group
    int b    = blockIdx.y;

    // map blockIdx.x -> (qtile qi, split p)
    int u = blockIdx.x, qi = 0, s = 1;
    for (qi = 0; qi < 32; qi++) {
        s = nsplits(qi);
        if (u < s) break;
        u -= s;
    }
    int p  = u;
    int n  = 2 * (qi + 1);
    int tb = p * 4;
    int te = (tb + 4 < n) ? tb + 4 : n;
    int r0 = qi * 128;
    int rA = r0 + 32 * w + g;     // mt0 first row; mt1 first row = rA+16

    u32 sKb[2] = { smem_u32(&sK[0][0]), smem_u32(&sK[1][0]) };
    u32 sVb[2] = { smem_u32(&sV[0][0]), smem_u32(&sV[1][0]) };

    // ldmatrix K address offset (per-lane)
    u32 klm = (u32)((lane & 7) * 64 + ((((lane >> 3) ^ (((lane & 7) >> 1) & 3))) << 4));
    // ldmatrix V lane mapping
    int vkey = (lane & 7) + 8 * ((lane >> 3) & 1);
    int vch  = (lane >> 4);

    // ones-column B fragment for l = P·1
    u32 bl = (g == 0) ? 0x3C003C00u : 0u;

    // ---- Q fragments for both m-tiles ----
    u32 qa[2][2][4];
#pragma unroll
    for (int mt = 0; mt < 2; mt++) {
        const __half* qA = g_q + ((size_t)b * TSEQ + rA + 16 * mt) * 32;
        const __half* qB = qA + 8 * 32;
#pragma unroll
        for (int ks = 0; ks < 2; ks++) {
            qa[mt][ks][0] = *(const u32*)(qA + 16 * ks + 2 * t4);
            qa[mt][ks][1] = *(const u32*)(qB + 16 * ks + 2 * t4);
            qa[mt][ks][2] = *(const u32*)(qA + 16 * ks + 2 * t4 + 8);
            qa[mt][ks][3] = *(const u32*)(qB + 16 * ks + 2 * t4 + 8);
        }
    }

    float oc[2][4][4];
#pragma unroll
    for (int mt = 0; mt < 2; mt++)
#pragma unroll
        for (int jd = 0; jd < 4; jd++)
#pragma unroll
            for (int q = 0; q < 4; q++) oc[mt][jd][q] = 0.f;
    float lc[2][4];
#pragma unroll
    for (int mt = 0; mt < 2; mt++)
#pragma unroll
        for (int q = 0; q < 4; q++) lc[mt][q] = 0.f;

    // ---- stage tile tb into buffer 0 ----
    {
        const char* kg = (const char*)(g_k + ((size_t)b * TSEQ + tb * 64) * 32);
        const char* vg = (const char*)(g_v + ((size_t)b * TSEQ + tb * 64) * 32);
#pragma unroll
        for (int i = 0; i < 2; i++) {
            int fi = tid + 128 * i;
            u32 st = (u32)((fi >> 2) * 64 + (((fi & 3) ^ ((fi >> 3) & 3)) << 4));
            u32 go = (u32)((fi >> 2) * 64 + (fi & 3) * 16);
            cpasync16(sKb[0] + st, kg + go);
            cpasync16(sVb[0] + st, vg + go);
        }
        CP_COMMIT();
    }

    int cur = 0;

    for (int t = tb; t < te; t++) {
        bool havenext = (t + 1 < te);
        if (havenext) {
            const char* kg = (const char*)(g_k + ((size_t)b * TSEQ + (t + 1) * 64) * 32);
            const char* vg = (const char*)(g_v + ((size_t)b * TSEQ + (t + 1) * 64) * 32);
#pragma unroll
            for (int i = 0; i < 2; i++) {
                int fi = tid + 128 * i;
                u32 st = (u32)((fi >> 2) * 64 + (((fi & 3) ^ ((fi >> 3) & 3)) << 4));
                u32 go = (u32)((fi >> 2) * 64 + (fi & 3) * 16);
                cpasync16(sKb[cur ^ 1] + st, kg + go);
                cpasync16(sVb[cur ^ 1] + st, vg + go);
            }
            CP_COMMIT();
            CP_WAIT(1);
        } else {
            CP_WAIT(0);
        }
        __syncthreads();

        u32 cK = sKb[cur];
        u32 cV = sVb[cur];
        bool domask = (t >= 2 * qi);

        // register double-buffered fragments for the 4 16-key groups
        u32 kb[2][8], vb[2][8];

        // ---- prologue: load group 0 fragments ----
        ldsm4(kb[0][0], kb[0][1], kb[0][2], kb[0][3], cK + klm);
        ldsm4(kb[0][4], kb[0][5], kb[0][6], kb[0][7], cK + 512 + klm);
        {
            int key = vkey;
            u32 vrow = cV + (u32)(key * 64);
            ldsm4t(vb[0][0], vb[0][1], vb[0][2], vb[0][3],
                   vrow + (u32)((vch ^ ((key >> 1) & 3)) << 4));
            ldsm4t(vb[0][4], vb[0][5], vb[0][6], vb[0][7],
                   vrow + (u32)(((vch + 2) ^ ((key >> 1) & 3)) << 4));
        }

#pragma unroll
        for (int c = 0; c < 4; c++) {
            int cb = c & 1, nb = cb ^ 1;

            // ---- S chains: 2 chunks x 2 m-tiles (4 independent) ----
            float s00[4] = {0.f, 0.f, 0.f, 0.f};   // mt0, chunk0
            float s10[4] = {0.f, 0.f, 0.f, 0.f};   // mt1, chunk0
            float s01[4] = {0.f, 0.f, 0.f, 0.f};   // mt0, chunk1
            float s11[4] = {0.f, 0.f, 0.f, 0.f};   // mt1, chunk1
            mma16(s00, qa[0][0], kb[cb][0], kb[cb][1]);
            mma16(s10, qa[1][0], kb[cb][0], kb[cb][1]);
            mma16(s01, qa[0][0], kb[cb][4], kb[cb][5]);
            mma16(s11, qa[1][0], kb[cb][4], kb[cb][5]);
            mma16(s00, qa[0][1], kb[cb][2], kb[cb][3]);
            mma16(s10, qa[1][1], kb[cb][2], kb[cb][3]);
            mma16(s01, qa[0][1], kb[cb][6], kb[cb][7]);
            mma16(s11, qa[1][1], kb[cb][6], kb[cb][7]);

            // ---- mask (pre-exp) ----
            int ct = t * 64 + 16 * c + 2 * t4;   // chunk0 key; chunk1 = ct+8
            if (domask) {
                if (ct      > rA)      s00[0] = -1e30f;
                if (ct + 1  > rA)      s00[1] = -1e30f;
                if (ct      > rA + 8)  s00[2] = -1e30f;
                if (ct + 1  > rA + 8)  s00[3] = -1e30f;
                if (ct      > rA + 16) s10[0] = -1e30f;
                if (ct + 1  > rA + 16) s10[1] = -1e30f;
                if (ct      > rA + 24) s10[2] = -1e30f;
                if (ct + 1  > rA + 24) s10[3] = -1e30f;
                if (ct + 8  > rA)      s01[0] = -1e30f;
                if (ct + 9  > rA)      s01[1] = -1e30f;
                if (ct + 8  > rA + 8)  s01[2] = -1e30f;
                if (ct + 9  > rA + 8)  s01[3] = -1e30f;
                if (ct + 8  > rA + 16) s11[0] = -1e30f;
                if (ct + 9  > rA + 16) s11[1] = -1e30f;
                if (ct + 8  > rA + 24) s11[2] = -1e30f;
                if (ct + 9  > rA + 24) s11[3] = -1e30f;
            }

            // ---- pack + packed exp -> P fragments ----
            u32 pa0[4], pa1[4];
            pa0[0] = h2exp(h2pack(s00[1], s00[0]));
            pa0[1] = h2exp(h2pack(s00[3], s00[2]));
            pa0[2] = h2exp(h2pack(s01[1], s01[0]));
            pa0[3] = h2exp(h2pack(s01[3], s01[2]));
            pa1[0] = h2exp(h2pack(s10[1], s10[0]));
            pa1[1] = h2exp(h2pack(s10[3], s10[2]));
            pa1[2] = h2exp(h2pack(s11[1], s11[0]));
            pa1[3] = h2exp(h2pack(s11[3], s11[2]));

            // ---- prefetch next group's fragments (hide under PV below) ----
            if (c < 3) {
                ldsm4(kb[nb][0], kb[nb][1], kb[nb][2], kb[nb][3],
                      cK + (u32)((2 * c + 2) * 512) + klm);
                ldsm4(kb[nb][4], kb[nb][5], kb[nb][6], kb[nb][7],
                      cK + (u32)((2 * c + 3) * 512) + klm);
                int key = (c + 1) * 16 + vkey;
                u32 vrow = cV + (u32)(key * 64);
                ldsm4t(vb[nb][0], vb[nb][1], vb[nb][2], vb[nb][3],
                       vrow + (u32)((vch ^ ((key >> 1) & 3)) << 4));
                ldsm4t(vb[nb][4], vb[nb][5], vb[nb][6], vb[nb][7],
                       vrow + (u32)(((vch + 2) ^ ((key >> 1) & 3)) << 4));
            }

            // ---- PV + l (10 mma; prefetch retires underneath) ----
            mma16(oc[0][0], pa0, vb[cb][0], vb[cb][1]);
            mma16(oc[1][0], pa1, vb[cb][0], vb[cb][1]);
            mma16(oc[0][1], pa0, vb[cb][2], vb[cb][3]);
            mma16(oc[1][1], pa1, vb[cb][2], vb[cb][3]);
            mma16(oc[0][2], pa0, vb[cb][4], vb[cb][5]);
            mma16(oc[1][2], pa1, vb[cb][4], vb[cb][5]);
            mma16(oc[0][3], pa0, vb[cb][6], vb[cb][7]);
            mma16(oc[1][3], pa1, vb[cb][6], vb[cb][7]);
            mma16(lc[0], pa0, bl, bl);
            mma16(lc[1], pa1, bl, bl);
        }

        __syncthreads();
        cur ^= 1;
    }

    // ---- row sums per m-tile (col 0 lanes broadcast) ----
    float ls0[2], ls1[2];
#pragma unroll
    for (int mt = 0; mt < 2; mt++) {
        ls0[mt] = __shfl_sync(0xffffffffu, lc[mt][0], lane & ~3);
        ls1[mt] = __shfl_sync(0xffffffffu, lc[mt][2], lane & ~3);
    }

    // ---- epilogue ----
    if (s == 1) {
#pragma unroll
        for (int mt = 0; mt < 2; mt++) {
            float i0 = 1.0f / ls0[mt];
            float i1 = 1.0f / ls1[mt];
            float* oA = out + ((size_t)b * TSEQ + rA + 16 * mt) * 32;
            float* oB = oA + 8 * 32;
#pragma unroll
            for (int jd = 0; jd < 4; jd++) {
                *(float2*)&oA[8 * jd + 2 * t4] =
                    make_float2(oc[mt][jd][0] * i0, oc[mt][jd][1] * i0);
                *(float2*)&oB[8 * jd + 2 * t4] =
                    make_float2(oc[mt][jd][2] * i1, oc[mt][jd][3] * i1);
            }
        }
    } else {
        size_t base = ((size_t)(b * 32 + qi) * 16 + p) * 128;
#pragma unroll
        for (int mt = 0; mt < 2; mt++) {
            int lr = 32 * w + 16 * mt + g;
            float* pA = g_po + (base + lr) * 32;
            float* pB = pA + 8 * 32;
#pragma unroll
            for (int jd = 0; jd < 4; jd++) {
                *(float2*)&pA[8 * jd + 2 * t4] = make_float2(oc[mt][jd][0], oc[mt][jd][1]);
                *(float2*)&pB[8 * jd + 2 * t4] = make_float2(oc[mt][jd][2], oc[mt][jd][3]);
            }
            if (t4 == 0) {
                g_pl[base + lr]     = ls0[mt];
                g_pl[base + lr + 8] = ls1[mt];
            }
        }
    }
}

// ---------------------------------------------------------------------------
// Kernel 3: combine split partials: out = sum_p O_p / sum_p l_p
// ---------------------------------------------------------------------------
__global__ __launch_bounds__(128) void combine_kernel(float* __restrict__ out)
{
    int qi = blockIdx.x, b = blockIdx.y, r = threadIdx.x;
    int s = nsplits(qi);
    if (s < 2) return;

    float l = 0.f;
    for (int p = 0; p < s; p++)
        l += g_pl[((size_t)(b * 32 + qi) * 16 + p) * 128 + r];
    float inv = 1.0f / l;

    float4 o[8];
#pragma unroll
    for (int j = 0; j < 8; j++) o[j] = make_float4(0.f, 0.f, 0.f, 0.f);
    for (int p = 0; p < s; p++) {
        const float4* pp = (const float4*)(g_po +
            (((size_t)(b * 32 + qi) * 16 + p) * 128 + r) * 32);
#pragma unroll
        for (int j = 0; j < 8; j++) {
            float4 a = pp[j];
            o[j].x += a.x; o[j].y += a.y; o[j].z += a.z; o[j].w += a.w;
        }
    }
    float4* op = (float4*)(out + ((size_t)b * TSEQ + qi * 128 + r) * 32);
#pragma unroll
    for (int j = 0; j < 8; j++) {
        o[j].x *= inv; o[j].y *= inv; o[j].z *= inv; o[j].w *= inv;
        op[j] = o[j];
    }
}

// ---------------------------------------------------------------------------
extern "C" void kernel_launch(void* const* d_in, const int* in_sizes, int n_in,
                              void* d_out, int out_size)
{
    const float* x  = (const float*)d_in[0];
    const float* Wq = (const float*)d_in[1];
    const float* Wk = (const float*)d_in[2];
    const float* Wv = (const float*)d_in[3];
    float* out = (float*)d_out;

    qkv_kernel<<<(BATCH * TSEQ) / 64, 128>>>(x, Wq, Wk, Wv);

    dim3 grid(272, BATCH);              // sum_i ceil((i+1)/2) = 272 per batch
    attn_kernel<<<grid, 128>>>(out);

    combine_kernel<<<dim3(32, BATCH), 128>>>(out);
}